// round 1
// baseline (speedup 1.0000x reference)
#include <cuda_runtime.h>
#include <math.h>

#define BB 8
#define TT 4096
#define DD 256
#define MM 1024
#define CTX 7
#define LL (TT - 1 + CTX)      /* 4102 */
#define NN (BB*TT)             /* 32768 */
#define QSIZE (NN*DD)          /* 8388608 */

// ---------------- scratch (static device globals; no runtime alloc) ----------
__device__ float g_xt[BB*DD*TT];          // x transposed [b][d][t]
__device__ float g_noisy[BB*DD*LL];       // padded+noised ctx input [b][i][l]
__device__ float g_ctxout[BB*DD*TT];      // conv output [b][o][t]
__device__ float g_curT[(size_t)DD*NN];   // fuse1 output transposed [o][n]
__device__ float g_G[(size_t)NN*MM];      // cur . E^T   [n][m]
__device__ float g_ET[DD*MM];             // E transposed [c][m]
__device__ float g_w1T[2*DD*DD];          // w_f1 transposed [k][o]
__device__ float g_w2T[2*DD*DD];          // w_f2 transposed [k][o]
__device__ float g_W2E[MM*DD];            // E . w_f2a^T  [m][o]
__device__ float g_esq[MM];
__device__ float g_scale[BB];
__device__ int   g_idx[NN];
__device__ unsigned int g_hist[MM];
__device__ float g_avgp[MM];

// ---------------- small utility kernels -------------------------------------
__global__ void k_zero() {
    int i = blockIdx.x*blockDim.x + threadIdx.x;
    if (i < MM) { g_hist[i] = 0u; g_avgp[i] = 0.f; }
}

// dst[c][r] = src[r][c];  which: 0 -> g_ET, 1 -> g_w1T, 2 -> g_w2T
__global__ void k_transp(const float* __restrict__ src, int rows, int cols, int which) {
    __shared__ float s[32][33];
    float* dst = (which == 0) ? g_ET : (which == 1) ? g_w1T : g_w2T;
    int c0 = blockIdx.x*32, r0 = blockIdx.y*32;
    int tx = threadIdx.x, ty = threadIdx.y;
    #pragma unroll
    for (int j = 0; j < 4; j++) {
        int r = r0 + ty + j*8, c = c0 + tx;
        s[ty + j*8][tx] = (r < rows && c < cols) ? src[(size_t)r*cols + c] : 0.f;
    }
    __syncthreads();
    #pragma unroll
    for (int j = 0; j < 4; j++) {
        int c = c0 + ty + j*8, r = r0 + tx;
        if (c < cols && r < rows) dst[(size_t)c*rows + r] = s[tx][ty + j*8];
    }
}

__global__ void k_esq(const float* __restrict__ E) {
    int warp = threadIdx.x >> 5, lane = threadIdx.x & 31;
    int m = blockIdx.x*8 + warp;
    const float* row = E + (size_t)m*DD;
    float s = 0.f;
    for (int c = lane; c < DD; c += 32) { float v = row[c]; s += v*v; }
    #pragma unroll
    for (int o = 16; o > 0; o >>= 1) s += __shfl_down_sync(0xffffffffu, s, o);
    if (lane == 0) g_esq[m] = s;
}

// scale[b] = 0.5 * sqrt(mean(ctx_in^2)) * 0.5^(epo/10)
__global__ void k_scale(const float* __restrict__ x, const int* __restrict__ epo_p) {
    int b = blockIdx.x;
    const float* xb = x + (size_t)b*TT*DD;
    float s = 0.f;
    int tot = (TT-1)*DD;
    for (int i = threadIdx.x; i < tot; i += blockDim.x) { float v = xb[i]; s += v*v; }
    __shared__ float sm[8];
    #pragma unroll
    for (int o = 16; o > 0; o >>= 1) s += __shfl_down_sync(0xffffffffu, s, o);
    if ((threadIdx.x & 31) == 0) sm[threadIdx.x >> 5] = s;
    __syncthreads();
    if (threadIdx.x == 0) {
        float t = 0.f;
        for (int w = 0; w < 8; w++) t += sm[w];
        int iv = epo_p[0];
        float ef = (iv >= 0 && iv < 100000) ? (float)iv : __int_as_float(iv); // defensive decode
        float sc = sqrtf(t / (float)(DD*LL));
        g_scale[b] = 0.5f * sc * exp2f(-ef * 0.1f);
    }
}

// g_xt[b][d][t] = x[b][t][d]
__global__ void k_xt(const float* __restrict__ x) {
    __shared__ float s[32][33];
    int b = blockIdx.z, t0 = blockIdx.x*32, d0 = blockIdx.y*32;
    int tx = threadIdx.x, ty = threadIdx.y;
    #pragma unroll
    for (int j = 0; j < 4; j++) {
        int t = t0 + ty + j*8;
        s[ty + j*8][tx] = x[((size_t)b*TT + t)*DD + d0 + tx];
    }
    __syncthreads();
    #pragma unroll
    for (int j = 0; j < 4; j++) {
        int d = d0 + ty + j*8;
        g_xt[((size_t)b*DD + d)*TT + t0 + tx] = s[tx][ty + j*8];
    }
}

// g_noisy[b][i][l] = (l>=7 && l-7 < T-1 ? x[b][l-7][i] : 0) + scale[b]*noise[b][i][l]
__global__ void k_noisy(const float* __restrict__ x, const float* __restrict__ noise) {
    __shared__ float s[32][33];
    int b = blockIdx.z, l0 = blockIdx.x*32, i0 = blockIdx.y*32;
    int tx = threadIdx.x, ty = threadIdx.y;
    float coef = g_scale[b];
    #pragma unroll
    for (int j = 0; j < 4; j++) {
        int row = ty + j*8;
        int t = l0 + row - CTX;
        float v = (t >= 0 && t < TT-1) ? x[((size_t)b*TT + t)*DD + i0 + tx] : 0.f;
        s[row][tx] = v;
    }
    __syncthreads();
    #pragma unroll
    for (int j = 0; j < 4; j++) {
        int i = i0 + ty + j*8, l = l0 + tx;
        if (l < LL) {
            size_t off = ((size_t)b*DD + i)*LL + l;
            g_noisy[off] = s[tx][ty + j*8] + coef * noise[off];
        }
    }
}

// ---------------- conv: ctx_out[b][o][t] = sum_{i,k} noisy[b][i][t+k] w[o][i][k]
__global__ void __launch_bounds__(256) k_conv(const float* __restrict__ wctx) {
    __shared__ float sW[112][68];   // [i_local*7+k][o_local]
    __shared__ float sIn[16][72];   // [i_local][t_local window]
    int b = blockIdx.z, t0 = blockIdx.x*64, o0 = blockIdx.y*64;
    int tid = threadIdx.x;
    int tx = tid & 15, ty = tid >> 4;
    float acc[4][4] = {};
    int ol = tid >> 2, seg = tid & 3;
    const float* wbase = wctx + (size_t)(o0 + ol)*(DD*CTX) + seg*28;
    const float* inb = g_noisy + ((size_t)b*DD)*LL + t0;

    for (int ic = 0; ic < DD; ic += 16) {
        const float* wp = wbase + ic*CTX;
        #pragma unroll
        for (int q = 0; q < 7; q++) {
            float4 v = *(const float4*)(wp + q*4);
            int z = seg*28 + q*4;
            sW[z+0][ol] = v.x; sW[z+1][ol] = v.y; sW[z+2][ol] = v.z; sW[z+3][ol] = v.w;
        }
        for (int idx = tid; idx < 16*70; idx += 256) {
            int il = idx / 70, j = idx - il*70;
            sIn[il][j] = inb[(size_t)(ic + il)*LL + j];
        }
        __syncthreads();
        #pragma unroll
        for (int il = 0; il < 16; il++) {
            float xw[10];
            float4 xa = *(const float4*)&sIn[il][4*tx];
            float4 xb4 = *(const float4*)&sIn[il][4*tx + 4];
            xw[0]=xa.x; xw[1]=xa.y; xw[2]=xa.z; xw[3]=xa.w;
            xw[4]=xb4.x; xw[5]=xb4.y; xw[6]=xb4.z; xw[7]=xb4.w;
            xw[8]=sIn[il][4*tx + 8]; xw[9]=sIn[il][4*tx + 9];
            #pragma unroll
            for (int kk = 0; kk < 7; kk++) {
                float4 wv = *(const float4*)&sW[il*7 + kk][4*ty];
                float wr[4] = {wv.x, wv.y, wv.z, wv.w};
                #pragma unroll
                for (int a = 0; a < 4; a++)
                    #pragma unroll
                    for (int c = 0; c < 4; c++)
                        acc[a][c] += wr[a] * xw[kk + c];
            }
        }
        __syncthreads();
    }
    #pragma unroll
    for (int a = 0; a < 4; a++) {
        int o = o0 + 4*ty + a;
        float4 v = make_float4(acc[a][0], acc[a][1], acc[a][2], acc[a][3]);
        *(float4*)&g_ctxout[((size_t)b*DD + o)*TT + t0 + 4*tx] = v;
    }
}

// ---------------- fuse1: curT[o][n] = prelu(sum_k w1T[k][o] * Acat[k][t], a1)
__global__ void __launch_bounds__(256) k_f1(const float* __restrict__ a1p) {
    __shared__ float sA[16][68];
    __shared__ float sB[16][68];
    int b = blockIdx.z, t0 = blockIdx.x*64, o0 = blockIdx.y*64;
    int tid = threadIdx.x;
    int tx = tid & 15, ty = tid >> 4;
    int kl = tid >> 4, nl4 = (tid & 15)*4;
    float acc[4][4] = {};
    for (int kc = 0; kc < 2*DD; kc += 16) {
        const float* Ap = (kc < DD) ? (g_xt + ((size_t)b*DD + kc)*TT)
                                    : (g_ctxout + ((size_t)b*DD + (kc - DD))*TT);
        *(float4*)&sA[kl][nl4] = *(const float4*)(Ap + (size_t)kl*TT + t0 + nl4);
        *(float4*)&sB[kl][nl4] = *(const float4*)(g_w1T + (size_t)(kc + kl)*DD + o0 + nl4);
        __syncthreads();
        #pragma unroll
        for (int k = 0; k < 16; k++) {
            float4 av = *(const float4*)&sA[k][4*tx];
            float4 bv = *(const float4*)&sB[k][4*ty];
            float ar[4] = {av.x, av.y, av.z, av.w};
            float br[4] = {bv.x, bv.y, bv.z, bv.w};
            #pragma unroll
            for (int a = 0; a < 4; a++)
                #pragma unroll
                for (int c = 0; c < 4; c++)
                    acc[a][c] += br[a] * ar[c];
        }
        __syncthreads();
    }
    float a1 = *a1p;
    size_t n0 = (size_t)b*TT + t0;
    #pragma unroll
    for (int a = 0; a < 4; a++) {
        int o = o0 + 4*ty + a;
        float4 v;
        float u;
        u = acc[a][0]; v.x = (u >= 0.f) ? u : a1*u;
        u = acc[a][1]; v.y = (u >= 0.f) ? u : a1*u;
        u = acc[a][2]; v.z = (u >= 0.f) ? u : a1*u;
        u = acc[a][3]; v.w = (u >= 0.f) ? u : a1*u;
        *(float4*)&g_curT[(size_t)o*NN + n0 + 4*tx] = v;
    }
}

// ---------------- generic TN GEMM: C[i][j] = sum_k A[k][i]*B[k][j], K=256
// which 0: W2E  (A=g_ET ldA=MM, B=g_w2T ldB=DD, C=g_W2E ldC=DD)
// which 1: dist (A=g_curT ldA=NN, B=g_ET ldB=MM, C=g_G ldC=MM)
__global__ void __launch_bounds__(256) k_gemm_tn(int which) {
    __shared__ float sA[16][68];
    __shared__ float sB[16][68];
    const float *A, *Bp; float* C; int ldA, ldB, ldC;
    if (which == 0) { A = g_ET;   ldA = MM; Bp = g_w2T; ldB = DD; C = g_W2E; ldC = DD; }
    else            { A = g_curT; ldA = NN; Bp = g_ET;  ldB = MM; C = g_G;   ldC = MM; }
    int i0 = blockIdx.x*64, j0 = blockIdx.y*64;
    int tid = threadIdx.x;
    int tx = tid & 15, ty = tid >> 4;
    int kl = tid >> 4, nl4 = (tid & 15)*4;
    float acc[4][4] = {};
    for (int kc = 0; kc < DD; kc += 16) {
        *(float4*)&sA[kl][nl4] = *(const float4*)(A  + (size_t)(kc + kl)*ldA + i0 + nl4);
        *(float4*)&sB[kl][nl4] = *(const float4*)(Bp + (size_t)(kc + kl)*ldB + j0 + nl4);
        __syncthreads();
        #pragma unroll
        for (int k = 0; k < 16; k++) {
            float4 av = *(const float4*)&sA[k][4*tx];
            float4 bv = *(const float4*)&sB[k][4*ty];
            float ar[4] = {av.x, av.y, av.z, av.w};
            float br[4] = {bv.x, bv.y, bv.z, bv.w};
            #pragma unroll
            for (int a = 0; a < 4; a++)
                #pragma unroll
                for (int c = 0; c < 4; c++)
                    acc[a][c] += br[a] * ar[c];
        }
        __syncthreads();
    }
    #pragma unroll
    for (int c = 0; c < 4; c++) {
        int i = i0 + 4*tx + c;
        float4 v = make_float4(acc[0][c], acc[1][c], acc[2][c], acc[3][c]);
        *(float4*)&C[(size_t)i*ldC + j0 + 4*ty] = v;
    }
}

// ---------------- per-row stats: argmax, softmax accum, gumbel argmax --------
__global__ void __launch_bounds__(256) k_rowstats(const float* __restrict__ gum,
                                                  float* __restrict__ out) {
    __shared__ float sAcc[MM];
    __shared__ float sEsq[MM];
    __shared__ float sV[256];
    __shared__ int   sI[256];
    int tid = threadIdx.x;
    for (int i = tid; i < MM; i += 256) { sAcc[i] = 0.f; sEsq[i] = g_esq[i]; }
    __syncthreads();

    for (int r = 0; r < 32; r++) {
        int n = blockIdx.x*32 + r;
        float4 gg = *(const float4*)&g_G[(size_t)n*MM + 4*tid];
        float dm[4];
        dm[0] = 2.f*gg.x - sEsq[4*tid + 0];
        dm[1] = 2.f*gg.y - sEsq[4*tid + 1];
        dm[2] = 2.f*gg.z - sEsq[4*tid + 2];
        dm[3] = 2.f*gg.w - sEsq[4*tid + 3];
        float4 uu = *(const float4*)(gum + (size_t)n*MM + 4*tid);
        float ur[4] = {uu.x, uu.y, uu.z, uu.w};
        float sc[4];
        #pragma unroll
        for (int j = 0; j < 4; j++) {
            float u = fminf(fmaxf(ur[j], 1e-10f), 1.f - 1e-7f);
            sc[j] = dm[j] - logf(-logf(u));
        }
        // thread-local argmaxes (lowest index wins on ties)
        float bv = dm[0]; int bi = 4*tid;
        #pragma unroll
        for (int j = 1; j < 4; j++) if (dm[j] > bv) { bv = dm[j]; bi = 4*tid + j; }
        float bsv = sc[0]; int bsi = 4*tid;
        #pragma unroll
        for (int j = 1; j < 4; j++) if (sc[j] > bsv) { bsv = sc[j]; bsi = 4*tid + j; }

        // block argmax over dm
        sV[tid] = bv; sI[tid] = bi; __syncthreads();
        for (int s = 128; s > 0; s >>= 1) {
            if (tid < s) {
                float v2 = sV[tid + s]; int i2 = sI[tid + s];
                if (v2 > sV[tid] || (v2 == sV[tid] && i2 < sI[tid])) { sV[tid] = v2; sI[tid] = i2; }
            }
            __syncthreads();
        }
        float maxdm = sV[0]; int kHard = sI[0];
        __syncthreads();

        // block argmax over gumbel scores
        sV[tid] = bsv; sI[tid] = bsi; __syncthreads();
        for (int s = 128; s > 0; s >>= 1) {
            if (tid < s) {
                float v2 = sV[tid + s]; int i2 = sI[tid + s];
                if (v2 > sV[tid] || (v2 == sV[tid] && i2 < sI[tid])) { sV[tid] = v2; sI[tid] = i2; }
            }
            __syncthreads();
        }
        int kSoft = sI[0];
        __syncthreads();

        // softmax(dm) accumulation
        float e[4], ls = 0.f;
        #pragma unroll
        for (int j = 0; j < 4; j++) { e[j] = expf(dm[j] - maxdm); ls += e[j]; }
        sV[tid] = ls; __syncthreads();
        for (int s = 128; s > 0; s >>= 1) {
            if (tid < s) sV[tid] += sV[tid + s];
            __syncthreads();
        }
        float inv = 1.f / sV[0];
        __syncthreads();
        #pragma unroll
        for (int j = 0; j < 4; j++) sAcc[4*tid + j] += e[j] * inv;

        if (tid == 0) {
            atomicAdd(&g_hist[kHard], 1u);
            g_idx[n] = kSoft;
            out[QSIZE + 2 + n] = (float)kSoft;
        }
    }
    __syncthreads();
    for (int i = tid; i < MM; i += 256) atomicAdd(&g_avgp[i], sAcc[i]);
}

__global__ void k_finalize(float* __restrict__ out) {
    __shared__ float s1[MM];
    __shared__ float s2[MM];
    int m = threadIdx.x;
    float hp = (float)g_hist[m] * (1.f/(float)NN);
    float ap = g_avgp[m] * (1.f/(float)NN);
    s1[m] = -hp * log2f(hp + 1e-10f);
    s2[m] = -ap * log2f(ap + 1e-10f);
    __syncthreads();
    for (int s = 512; s > 0; s >>= 1) {
        if (m < s) { s1[m] += s1[m + s]; s2[m] += s2[m + s]; }
        __syncthreads();
    }
    if (m == 0) { out[QSIZE] = s1[0]; out[QSIZE + 1] = s2[0]; }
}

// ---------------- fuse2: out[n][o] = prelu(sum_k w2T[256+k][o]*ctx[b][k][t] + W2E[idx[n]][o], a2)
__global__ void __launch_bounds__(256) k_f2(const float* __restrict__ a2p,
                                            float* __restrict__ out) {
    __shared__ float sA[16][68];
    __shared__ float sB[16][68];
    int b = blockIdx.z, t0 = blockIdx.x*64, o0 = blockIdx.y*64;
    int tid = threadIdx.x;
    int tx = tid & 15, ty = tid >> 4;
    int kl = tid >> 4, nl4 = (tid & 15)*4;
    float acc[4][4] = {};
    const float* Ab = g_ctxout + (size_t)b*DD*TT;
    for (int kc = 0; kc < DD; kc += 16) {
        *(float4*)&sA[kl][nl4] = *(const float4*)(Ab + (size_t)(kc + kl)*TT + t0 + nl4);
        *(float4*)&sB[kl][nl4] = *(const float4*)(g_w2T + (size_t)(DD + kc + kl)*DD + o0 + nl4);
        __syncthreads();
        #pragma unroll
        for (int k = 0; k < 16; k++) {
            float4 av = *(const float4*)&sA[k][4*tx];
            float4 bv = *(const float4*)&sB[k][4*ty];
            float ar[4] = {av.x, av.y, av.z, av.w};
            float br[4] = {bv.x, bv.y, bv.z, bv.w};
            #pragma unroll
            for (int a = 0; a < 4; a++)
                #pragma unroll
                for (int c = 0; c < 4; c++)
                    acc[a][c] += br[a] * ar[c];
        }
        __syncthreads();
    }
    float a2 = *a2p;
    #pragma unroll
    for (int c = 0; c < 4; c++) {
        size_t n = (size_t)b*TT + t0 + 4*tx + c;
        int mi = g_idx[n];
        float4 wv = *(const float4*)&g_W2E[(size_t)mi*DD + o0 + 4*ty];
        float wr[4] = {wv.x, wv.y, wv.z, wv.w};
        float4 v;
        float u;
        u = acc[0][c] + wr[0]; v.x = (u >= 0.f) ? u : a2*u;
        u = acc[1][c] + wr[1]; v.y = (u >= 0.f) ? u : a2*u;
        u = acc[2][c] + wr[2]; v.z = (u >= 0.f) ? u : a2*u;
        u = acc[3][c] + wr[3]; v.w = (u >= 0.f) ? u : a2*u;
        *(float4*)&out[n*DD + o0 + 4*ty] = v;
    }
}

// ---------------- launch -----------------------------------------------------
extern "C" void kernel_launch(void* const* d_in, const int* in_sizes, int n_in,
                              void* d_out, int out_size) {
    const float* x     = (const float*)d_in[0];
    const float* noise = (const float*)d_in[1];
    const float* gum   = (const float*)d_in[2];
    const int*   epo   = (const int*)  d_in[3];
    const float* emb   = (const float*)d_in[4];
    const float* wctx  = (const float*)d_in[5];
    const float* wf1   = (const float*)d_in[6];
    const float* a1    = (const float*)d_in[7];
    const float* wf2   = (const float*)d_in[8];
    const float* a2    = (const float*)d_in[9];
    float* out = (float*)d_out;

    dim3 tb32(32, 8);

    k_zero<<<4, 256>>>();
    k_transp<<<dim3(DD/32, MM/32), tb32>>>(emb, MM, DD, 0);      // E -> ET
    k_transp<<<dim3(2*DD/32, DD/32), tb32>>>(wf1, DD, 2*DD, 1);  // w_f1 -> w1T
    k_transp<<<dim3(2*DD/32, DD/32), tb32>>>(wf2, DD, 2*DD, 2);  // w_f2 -> w2T
    k_esq<<<MM/8, 256>>>(emb);
    k_scale<<<BB, 256>>>(x, epo);
    k_xt<<<dim3(TT/32, DD/32, BB), tb32>>>(x);
    k_noisy<<<dim3((LL + 31)/32, DD/32, BB), tb32>>>(x, noise);
    k_conv<<<dim3(TT/64, DD/64, BB), 256>>>(wctx);
    k_f1<<<dim3(TT/64, DD/64, BB), 256>>>(a1);
    k_gemm_tn<<<dim3(MM/64, DD/64), 256>>>(0);   // W2E
    k_gemm_tn<<<dim3(NN/64, MM/64), 256>>>(1);   // dist
    k_rowstats<<<NN/32, 256>>>(gum, out);
    k_finalize<<<1, MM>>>(out);
    k_f2<<<dim3(TT/64, DD/64, BB), 256>>>(a2, out);
}

// round 4
// speedup vs baseline: 1.0292x; 1.0292x over previous
#include <cuda_runtime.h>
#include <math.h>
#include <stdint.h>

#define BB 8
#define TT 4096
#define DD 256
#define MM 1024
#define CTX 7
#define LL (TT - 1 + CTX)      /* 4102 */
#define NN (BB*TT)             /* 32768 */
#define QSIZE (NN*DD)          /* 8388608 */

// ---------------- scratch (static device globals; no runtime alloc) ----------
__device__ __align__(16) float g_xt[BB*DD*TT];          // x transposed [b][d][t]
__device__ __align__(16) float g_noisy[BB*DD*LL];       // padded+noised ctx input
__device__ __align__(16) float g_ctxout[BB*DD*TT];      // conv output [b][o][t]
__device__ __align__(16) float g_cur[(size_t)NN*DD];    // fuse1 out [n][c], exact fp32
__device__ __align__(16) float g_cur_hi[(size_t)NN*DD]; // tf32-hi
__device__ __align__(16) float g_cur_lo[(size_t)NN*DD]; // residual (tf32)
__device__ __align__(16) float g_E_hi[MM*DD];
__device__ __align__(16) float g_E_lo[MM*DD];
__device__ __align__(16) float g_G[(size_t)NN*MM];      // cur . E^T   [n][m]
__device__ __align__(16) float g_ET[DD*MM];             // E transposed [c][m]
__device__ __align__(16) float g_w1T[2*DD*DD];          // w_f1 transposed [k][o]
__device__ __align__(16) float g_w2T[2*DD*DD];          // w_f2 transposed [k][o]
__device__ __align__(16) float g_W2E[MM*DD];            // E . w_f2a^T  [m][o]
__device__ __align__(16) float g_esq[MM];
__device__ float g_scale[BB];
__device__ int   g_idx[NN];
__device__ unsigned int g_hist[MM];
__device__ float g_avgp[MM];

__device__ __forceinline__ float tf32_hi(float v) {
    uint32_t b;
    asm("cvt.rna.tf32.f32 %0, %1;" : "=r"(b) : "f"(v));
    return __uint_as_float(b);
}

// ---------------- small utility kernels -------------------------------------
__global__ void k_zero() {
    int i = blockIdx.x*blockDim.x + threadIdx.x;
    if (i < MM) { g_hist[i] = 0u; g_avgp[i] = 0.f; }
}

// dst[c][r] = src[r][c];  which: 0 -> g_ET, 1 -> g_w1T, 2 -> g_w2T
__global__ void k_transp(const float* __restrict__ src, int rows, int cols, int which) {
    __shared__ float s[32][33];
    float* dst = (which == 0) ? g_ET : (which == 1) ? g_w1T : g_w2T;
    int c0 = blockIdx.x*32, r0 = blockIdx.y*32;
    int tx = threadIdx.x, ty = threadIdx.y;
    #pragma unroll
    for (int j = 0; j < 4; j++) {
        int r = r0 + ty + j*8, c = c0 + tx;
        s[ty + j*8][tx] = (r < rows && c < cols) ? src[(size_t)r*cols + c] : 0.f;
    }
    __syncthreads();
    #pragma unroll
    for (int j = 0; j < 4; j++) {
        int c = c0 + ty + j*8, r = r0 + tx;
        if (c < cols && r < rows) dst[(size_t)c*rows + r] = s[tx][ty + j*8];
    }
}

__global__ void k_esq(const float* __restrict__ E) {
    int warp = threadIdx.x >> 5, lane = threadIdx.x & 31;
    int m = blockIdx.x*8 + warp;
    const float* row = E + (size_t)m*DD;
    float s = 0.f;
    for (int c = lane; c < DD; c += 32) { float v = row[c]; s += v*v; }
    #pragma unroll
    for (int o = 16; o > 0; o >>= 1) s += __shfl_down_sync(0xffffffffu, s, o);
    if (lane == 0) g_esq[m] = s;
}

__global__ void k_split_e(const float* __restrict__ E) {
    int i = blockIdx.x*256 + threadIdx.x;   // grid 1024
    float v = E[i];
    float h = tf32_hi(v);
    g_E_hi[i] = h;
    g_E_lo[i] = tf32_hi(v - h);
}

// scale[b] = 0.5 * sqrt(mean(ctx_in^2)) * 0.5^(epo/10)
__global__ void k_scale(const float* __restrict__ x, const int* __restrict__ epo_p) {
    int b = blockIdx.x;
    const float* xb = x + (size_t)b*TT*DD;
    float s = 0.f;
    int tot = (TT-1)*DD;
    for (int i = threadIdx.x; i < tot; i += blockDim.x) { float v = xb[i]; s += v*v; }
    __shared__ float sm[8];
    #pragma unroll
    for (int o = 16; o > 0; o >>= 1) s += __shfl_down_sync(0xffffffffu, s, o);
    if ((threadIdx.x & 31) == 0) sm[threadIdx.x >> 5] = s;
    __syncthreads();
    if (threadIdx.x == 0) {
        float t = 0.f;
        for (int w = 0; w < 8; w++) t += sm[w];
        int iv = epo_p[0];
        float ef = (iv >= 0 && iv < 100000) ? (float)iv : __int_as_float(iv);
        float sc = sqrtf(t / (float)(DD*LL));
        g_scale[b] = 0.5f * sc * exp2f(-ef * 0.1f);
    }
}

// g_xt[b][d][t] = x[b][t][d]
__global__ void k_xt(const float* __restrict__ x) {
    __shared__ float s[32][33];
    int b = blockIdx.z, t0 = blockIdx.x*32, d0 = blockIdx.y*32;
    int tx = threadIdx.x, ty = threadIdx.y;
    #pragma unroll
    for (int j = 0; j < 4; j++) {
        int t = t0 + ty + j*8;
        s[ty + j*8][tx] = x[((size_t)b*TT + t)*DD + d0 + tx];
    }
    __syncthreads();
    #pragma unroll
    for (int j = 0; j < 4; j++) {
        int d = d0 + ty + j*8;
        g_xt[((size_t)b*DD + d)*TT + t0 + tx] = s[tx][ty + j*8];
    }
}

__global__ void k_noisy(const float* __restrict__ x, const float* __restrict__ noise) {
    __shared__ float s[32][33];
    int b = blockIdx.z, l0 = blockIdx.x*32, i0 = blockIdx.y*32;
    int tx = threadIdx.x, ty = threadIdx.y;
    float coef = g_scale[b];
    #pragma unroll
    for (int j = 0; j < 4; j++) {
        int row = ty + j*8;
        int t = l0 + row - CTX;
        float v = (t >= 0 && t < TT-1) ? x[((size_t)b*TT + t)*DD + i0 + tx] : 0.f;
        s[row][tx] = v;
    }
    __syncthreads();
    #pragma unroll
    for (int j = 0; j < 4; j++) {
        int i = i0 + ty + j*8, l = l0 + tx;
        if (l < LL) {
            size_t off = ((size_t)b*DD + i)*LL + l;
            g_noisy[off] = s[tx][ty + j*8] + coef * noise[off];
        }
    }
}

// ---------------- conv: ctx_out[b][o][t] = sum_{i,k} noisy[b][i][t+k] w[o][i][k]
__global__ void __launch_bounds__(256) k_conv(const float* __restrict__ wctx) {
    __shared__ float sW[112][68];
    __shared__ float sIn[16][72];
    int b = blockIdx.z, t0 = blockIdx.x*64, o0 = blockIdx.y*64;
    int tid = threadIdx.x;
    int tx = tid & 15, ty = tid >> 4;
    float acc[4][4] = {};
    int ol = tid >> 2, seg = tid & 3;
    const float* wbase = wctx + (size_t)(o0 + ol)*(DD*CTX) + seg*28;
    const float* inb = g_noisy + ((size_t)b*DD)*LL + t0;

    for (int ic = 0; ic < DD; ic += 16) {
        const float* wp = wbase + ic*CTX;
        #pragma unroll
        for (int q = 0; q < 7; q++) {
            float4 v = *(const float4*)(wp + q*4);
            int z = seg*28 + q*4;
            sW[z+0][ol] = v.x; sW[z+1][ol] = v.y; sW[z+2][ol] = v.z; sW[z+3][ol] = v.w;
        }
        for (int idx = tid; idx < 16*70; idx += 256) {
            int il = idx / 70, j = idx - il*70;
            sIn[il][j] = inb[(size_t)(ic + il)*LL + j];
        }
        __syncthreads();
        #pragma unroll
        for (int il = 0; il < 16; il++) {
            float xw[10];
            float4 xa = *(const float4*)&sIn[il][4*tx];
            float4 xb4 = *(const float4*)&sIn[il][4*tx + 4];
            xw[0]=xa.x; xw[1]=xa.y; xw[2]=xa.z; xw[3]=xa.w;
            xw[4]=xb4.x; xw[5]=xb4.y; xw[6]=xb4.z; xw[7]=xb4.w;
            xw[8]=sIn[il][4*tx + 8]; xw[9]=sIn[il][4*tx + 9];
            #pragma unroll
            for (int kk = 0; kk < 7; kk++) {
                float4 wv = *(const float4*)&sW[il*7 + kk][4*ty];
                float wr[4] = {wv.x, wv.y, wv.z, wv.w};
                #pragma unroll
                for (int a = 0; a < 4; a++)
                    #pragma unroll
                    for (int c = 0; c < 4; c++)
                        acc[a][c] += wr[a] * xw[kk + c];
            }
        }
        __syncthreads();
    }
    #pragma unroll
    for (int a = 0; a < 4; a++) {
        int o = o0 + 4*ty + a;
        float4 v = make_float4(acc[a][0], acc[a][1], acc[a][2], acc[a][3]);
        *(float4*)&g_ctxout[((size_t)b*DD + o)*TT + t0 + 4*tx] = v;
    }
}

// ---------------- fuse1: cur[n][o] = prelu(sum_k w1T[k][o]*Acat[k][t], a1)
// writes exact cur + tf32 hi/lo split
__global__ void __launch_bounds__(256) k_f1(const float* __restrict__ a1p) {
    __shared__ float sA[16][68];
    __shared__ float sB[16][68];
    int b = blockIdx.z, t0 = blockIdx.x*64, o0 = blockIdx.y*64;
    int tid = threadIdx.x;
    int tx = tid & 15, ty = tid >> 4;
    int kl = tid >> 4, nl4 = (tid & 15)*4;
    float acc[4][4] = {};
    for (int kc = 0; kc < 2*DD; kc += 16) {
        const float* Ap = (kc < DD) ? (g_xt + ((size_t)b*DD + kc)*TT)
                                    : (g_ctxout + ((size_t)b*DD + (kc - DD))*TT);
        *(float4*)&sA[kl][nl4] = *(const float4*)(Ap + (size_t)kl*TT + t0 + nl4);
        *(float4*)&sB[kl][nl4] = *(const float4*)(g_w1T + (size_t)(kc + kl)*DD + o0 + nl4);
        __syncthreads();
        #pragma unroll
        for (int k = 0; k < 16; k++) {
            float4 av = *(const float4*)&sA[k][4*tx];
            float4 bv = *(const float4*)&sB[k][4*ty];
            float ar[4] = {av.x, av.y, av.z, av.w};
            float br[4] = {bv.x, bv.y, bv.z, bv.w};
            #pragma unroll
            for (int a = 0; a < 4; a++)
                #pragma unroll
                for (int c = 0; c < 4; c++)
                    acc[a][c] += br[a] * ar[c];
        }
        __syncthreads();
    }
    float a1 = *a1p;
    #pragma unroll
    for (int c = 0; c < 4; c++) {
        size_t n = (size_t)b*TT + t0 + 4*tx + c;
        float4 ve, vh, vl;
        float u, h;
        u = acc[0][c]; u = (u >= 0.f) ? u : a1*u; ve.x = u; h = tf32_hi(u); vh.x = h; vl.x = tf32_hi(u - h);
        u = acc[1][c]; u = (u >= 0.f) ? u : a1*u; ve.y = u; h = tf32_hi(u); vh.y = h; vl.y = tf32_hi(u - h);
        u = acc[2][c]; u = (u >= 0.f) ? u : a1*u; ve.z = u; h = tf32_hi(u); vh.z = h; vl.z = tf32_hi(u - h);
        u = acc[3][c]; u = (u >= 0.f) ? u : a1*u; ve.w = u; h = tf32_hi(u); vh.w = h; vl.w = tf32_hi(u - h);
        *(float4*)&g_cur[n*DD + o0 + 4*ty] = ve;
        *(float4*)&g_cur_hi[n*DD + o0 + 4*ty] = vh;
        *(float4*)&g_cur_lo[n*DD + o0 + 4*ty] = vl;
    }
}

// ---------------- W2E GEMM (small): C[m][o] = sum_c ET[c][m] w2T[c][o]
__global__ void __launch_bounds__(256) k_gemm_w2e() {
    __shared__ float sA[16][68];
    __shared__ float sB[16][68];
    int i0 = blockIdx.x*64, j0 = blockIdx.y*64;
    int tid = threadIdx.x;
    int tx = tid & 15, ty = tid >> 4;
    int kl = tid >> 4, nl4 = (tid & 15)*4;
    float acc[4][4] = {};
    for (int kc = 0; kc < DD; kc += 16) {
        *(float4*)&sA[kl][nl4] = *(const float4*)(g_ET  + (size_t)(kc + kl)*MM + i0 + nl4);
        *(float4*)&sB[kl][nl4] = *(const float4*)(g_w2T + (size_t)(kc + kl)*DD + j0 + nl4);
        __syncthreads();
        #pragma unroll
        for (int k = 0; k < 16; k++) {
            float4 av = *(const float4*)&sA[k][4*tx];
            float4 bv = *(const float4*)&sB[k][4*ty];
            float ar[4] = {av.x, av.y, av.z, av.w};
            float br[4] = {bv.x, bv.y, bv.z, bv.w};
            #pragma unroll
            for (int a = 0; a < 4; a++)
                #pragma unroll
                for (int c = 0; c < 4; c++)
                    acc[a][c] += br[a] * ar[c];
        }
        __syncthreads();
    }
    #pragma unroll
    for (int c = 0; c < 4; c++) {
        int i = i0 + 4*tx + c;
        float4 v = make_float4(acc[0][c], acc[1][c], acc[2][c], acc[3][c]);
        *(float4*)&g_W2E[(size_t)i*DD + j0 + 4*ty] = v;
    }
}

// ---------------- dist GEMM via mma.sync tf32 (3xTF32) -----------------------
#define D_ARRF 4096                       /* floats per array */
#define D_SMEMB (2*4*D_ARRF*4)            /* 131072 bytes */

__device__ __forceinline__ int swz(int r, int c) {
    return r*32 + ((((c >> 2) ^ (r & 7)) << 2) | (c & 3));
}

#define MMA8(d, a0,a1,a2,a3, b0,b1) \
    asm volatile("mma.sync.aligned.m16n8k8.row.col.f32.tf32.tf32.f32 " \
        "{%0,%1,%2,%3}, {%4,%5,%6,%7}, {%8,%9}, {%0,%1,%2,%3};" \
        : "+f"((d)[0]), "+f"((d)[1]), "+f"((d)[2]), "+f"((d)[3]) \
        : "r"(a0), "r"(a1), "r"(a2), "r"(a3), "r"(b0), "r"(b1))

__global__ void __launch_bounds__(256) k_dist_mma() {
    extern __shared__ float sm[];
    int tid = threadIdx.x, lane = tid & 31, warp = tid >> 5;
    int warpM = warp >> 2, warpN = warp & 3;       // 2 x 4
    int n0 = blockIdx.x*128, m0 = blockIdx.y*128;

    uint32_t sbase;
    asm("{ .reg .u64 t; cvta.to.shared.u64 t, %1; cvt.u32.u64 %0, t; }" : "=r"(sbase) : "l"(sm));

    const float* srcs[4] = { g_cur_hi + (size_t)n0*DD, g_cur_lo + (size_t)n0*DD,
                             g_E_hi   + (size_t)m0*DD, g_E_lo   + (size_t)m0*DD };
    int lr = tid >> 3, c4 = tid & 7;

    auto issue = [&](int kc, int s) {
        #pragma unroll
        for (int a = 0; a < 4; a++) {
            const float* srcb = srcs[a] + kc + c4*4;
            uint32_t dstb = sbase + (uint32_t)(((s*4 + a)*D_ARRF)*4);
            #pragma unroll
            for (int j = 0; j < 4; j++) {
                int row = lr + 32*j;
                uint32_t dst = dstb + (uint32_t)((row*32 + ((c4 ^ (row & 7)) << 2))*4);
                const float* src = srcb + (size_t)row*DD;
                asm volatile("cp.async.cg.shared.global [%0], [%1], 16;"
                             :: "r"(dst), "l"(src));
            }
        }
        asm volatile("cp.async.commit_group;");
    };

    float c[4][4][4] = {};
    issue(0, 0);

    for (int it = 0; it < 8; it++) {
        int s = it & 1;
        if (it + 1 < 8) issue((it + 1)*32, s ^ 1);
        if (it + 1 < 8) { asm volatile("cp.async.wait_group 1;"); }
        else            { asm volatile("cp.async.wait_group 0;"); }
        __syncthreads();

        const float* sAh = sm + (s*4 + 0)*D_ARRF;
        const float* sAl = sm + (s*4 + 1)*D_ARRF;
        const float* sBh = sm + (s*4 + 2)*D_ARRF;
        const float* sBl = sm + (s*4 + 3)*D_ARRF;

        #pragma unroll
        for (int ks = 0; ks < 4; ks++) {
            int ca = ks*8 + (lane & 3);
            uint32_t Ah[16], Al[16], Bh[8], Bl[8];
            #pragma unroll
            for (int mf = 0; mf < 4; mf++) {
                int r1 = warpM*64 + mf*16 + (lane >> 2), r2 = r1 + 8;
                Ah[mf*4+0] = __float_as_uint(sAh[swz(r1, ca)]);
                Ah[mf*4+1] = __float_as_uint(sAh[swz(r2, ca)]);
                Ah[mf*4+2] = __float_as_uint(sAh[swz(r1, ca + 4)]);
                Ah[mf*4+3] = __float_as_uint(sAh[swz(r2, ca + 4)]);
                Al[mf*4+0] = __float_as_uint(sAl[swz(r1, ca)]);
                Al[mf*4+1] = __float_as_uint(sAl[swz(r2, ca)]);
                Al[mf*4+2] = __float_as_uint(sAl[swz(r1, ca + 4)]);
                Al[mf*4+3] = __float_as_uint(sAl[swz(r2, ca + 4)]);
            }
            #pragma unroll
            for (int nf = 0; nf < 4; nf++) {
                int rm = warpN*32 + nf*8 + (lane >> 2);
                Bh[nf*2+0] = __float_as_uint(sBh[swz(rm, ca)]);
                Bh[nf*2+1] = __float_as_uint(sBh[swz(rm, ca + 4)]);
                Bl[nf*2+0] = __float_as_uint(sBl[swz(rm, ca)]);
                Bl[nf*2+1] = __float_as_uint(sBl[swz(rm, ca + 4)]);
            }
            #pragma unroll
            for (int mf = 0; mf < 4; mf++) {
                #pragma unroll
                for (int nf = 0; nf < 4; nf++) {
                    MMA8(c[mf][nf], Ah[mf*4+0], Ah[mf*4+1], Ah[mf*4+2], Ah[mf*4+3],
                         Bh[nf*2+0], Bh[nf*2+1]);
                    MMA8(c[mf][nf], Ah[mf*4+0], Ah[mf*4+1], Ah[mf*4+2], Ah[mf*4+3],
                         Bl[nf*2+0], Bl[nf*2+1]);
                    MMA8(c[mf][nf], Al[mf*4+0], Al[mf*4+1], Al[mf*4+2], Al[mf*4+3],
                         Bh[nf*2+0], Bh[nf*2+1]);
                }
            }
        }
        __syncthreads();
    }

    #pragma unroll
    for (int mf = 0; mf < 4; mf++) {
        int r1 = n0 + warpM*64 + mf*16 + (lane >> 2);
        #pragma unroll
        for (int nf = 0; nf < 4; nf++) {
            int gc = m0 + warpN*32 + nf*8 + (lane & 3)*2;
            float2 v0 = make_float2(c[mf][nf][0], c[mf][nf][1]);
            float2 v1 = make_float2(c[mf][nf][2], c[mf][nf][3]);
            *(float2*)&g_G[(size_t)r1*MM + gc] = v0;
            *(float2*)&g_G[(size_t)(r1 + 8)*MM + gc] = v1;
        }
    }
}

// ---------------- per-row stats with exact top-2 refinement -----------------
__device__ __forceinline__ float gumbel_of(float u) {
    u = fminf(fmaxf(u, 1e-10f), 1.f - 1e-7f);
    return -logf(-logf(u));
}

__global__ void __launch_bounds__(256) k_rowstats(const float* __restrict__ gum,
                                                  const float* __restrict__ emb,
                                                  float* __restrict__ out) {
    __shared__ float sAcc[MM];
    int tid = threadIdx.x, wid = tid >> 5, lane = tid & 31;
    for (int i = tid; i < MM; i += 256) sAcc[i] = 0.f;
    __syncthreads();

    float esq_r[8][4];
    #pragma unroll
    for (int ch = 0; ch < 8; ch++) {
        float4 v = *(const float4*)&g_esq[ch*128 + lane*4];
        esq_r[ch][0] = v.x; esq_r[ch][1] = v.y; esq_r[ch][2] = v.z; esq_r[ch][3] = v.w;
    }
    float pAcc[8][4] = {};
    int nbase = blockIdx.x*128 + wid*16;

    for (int r = 0; r < 16; r++) {
        int n = nbase + r;
        const float* Gr = g_G + (size_t)n*MM;
        const float* Ur = gum + (size_t)n*MM;
        float dm[8][4];
        // top-2 trackers: h* = hard (dm), s* = gumbel score
        float h1v = -3.4e38f, h2v = -3.4e38f; int h1i = 0x7fffffff, h2i = 0x7fffffff;
        float s1v = -3.4e38f, s2v = -3.4e38f; int s1i = 0x7fffffff, s2i = 0x7fffffff;
        #pragma unroll
        for (int ch = 0; ch < 8; ch++) {
            float4 g4 = *(const float4*)&Gr[ch*128 + lane*4];
            float4 u4 = *(const float4*)&Ur[ch*128 + lane*4];
            float gg[4] = {g4.x, g4.y, g4.z, g4.w};
            float uu[4] = {u4.x, u4.y, u4.z, u4.w};
            #pragma unroll
            for (int j = 0; j < 4; j++) {
                int m = ch*128 + lane*4 + j;
                float d = 2.f*gg[j] - esq_r[ch][j];
                dm[ch][j] = d;
                if (d > h1v || (d == h1v && m < h1i)) { h2v = h1v; h2i = h1i; h1v = d; h1i = m; }
                else if (d > h2v || (d == h2v && m < h2i)) { h2v = d; h2i = m; }
                float sc = d + gumbel_of(uu[j]);
                if (sc > s1v || (sc == s1v && m < s1i)) { s2v = s1v; s2i = s1i; s1v = sc; s1i = m; }
                else if (sc > s2v || (sc == s2v && m < s2i)) { s2v = sc; s2i = m; }
            }
        }
        // warp top-2 merge (both criteria)
        #pragma unroll
        for (int o = 16; o > 0; o >>= 1) {
            float ov1 = __shfl_xor_sync(0xffffffffu, h1v, o);
            int   oi1 = __shfl_xor_sync(0xffffffffu, h1i, o);
            float ov2 = __shfl_xor_sync(0xffffffffu, h2v, o);
            int   oi2 = __shfl_xor_sync(0xffffffffu, h2i, o);
            if (ov1 > h1v || (ov1 == h1v && oi1 < h1i)) {
                float t1v = h1v; int t1i = h1i;
                h1v = ov1; h1i = oi1;
                if (t1v > ov2 || (t1v == ov2 && t1i < oi2)) { h2v = t1v; h2i = t1i; }
                else { h2v = ov2; h2i = oi2; }
            } else {
                if (ov1 > h2v || (ov1 == h2v && oi1 < h2i)) { h2v = ov1; h2i = oi1; }
            }
            float pv1 = __shfl_xor_sync(0xffffffffu, s1v, o);
            int   pi1 = __shfl_xor_sync(0xffffffffu, s1i, o);
            float pv2 = __shfl_xor_sync(0xffffffffu, s2v, o);
            int   pi2 = __shfl_xor_sync(0xffffffffu, s2i, o);
            if (pv1 > s1v || (pv1 == s1v && pi1 < s1i)) {
                float t1v = s1v; int t1i = s1i;
                s1v = pv1; s1i = pi1;
                if (t1v > pv2 || (t1v == pv2 && t1i < pi2)) { s2v = t1v; s2i = t1i; }
                else { s2v = pv2; s2i = pi2; }
            } else {
                if (pv1 > s2v || (pv1 == s2v && pi1 < s2i)) { s2v = pv1; s2i = pi1; }
            }
        }

        // exact fp32 refinement of the 4 candidates
        int cands[4] = {h1i, h2i, s1i, s2i};
        float ex[4];
        const float* curp = g_cur + (size_t)n*DD + lane*8;
        #pragma unroll
        for (int t = 0; t < 4; t++) {
            const float* Ep = emb + (size_t)cands[t]*DD + lane*8;
            float s = 0.f;
            #pragma unroll
            for (int j = 0; j < 8; j++) s += curp[j]*Ep[j];
            #pragma unroll
            for (int o = 16; o > 0; o >>= 1) s += __shfl_xor_sync(0xffffffffu, s, o);
            ex[t] = 2.f*s - g_esq[cands[t]];
        }

        // softmax(dm) accumulation (noisy dm fine; shift by noisy max)
        float ssum = 0.f;
        #pragma unroll
        for (int ch = 0; ch < 8; ch++)
            #pragma unroll
            for (int j = 0; j < 4; j++) ssum += expf(dm[ch][j] - h1v);
        #pragma unroll
        for (int o = 16; o > 0; o >>= 1) ssum += __shfl_xor_sync(0xffffffffu, ssum, o);
        float inv = 1.f / ssum;
        #pragma unroll
        for (int ch = 0; ch < 8; ch++)
            #pragma unroll
            for (int j = 0; j < 4; j++) pAcc[ch][j] += expf(dm[ch][j] - h1v) * inv;

        if (lane == 0) {
            // hard winner (exact)
            int kH = h1i; float vH = ex[0];
            if (ex[1] > vH || (ex[1] == vH && h2i < kH)) { kH = h2i; vH = ex[1]; }
            atomicAdd(&g_hist[kH], 1u);
            // gumbel winner (exact)
            float sc0 = ex[2] + gumbel_of(Ur[s1i]);
            float sc1 = ex[3] + gumbel_of(Ur[s2i]);
            int kS = s1i;
            if (sc1 > sc0 || (sc1 == sc0 && s2i < s1i)) kS = s2i;
            g_idx[n] = kS;
            out[QSIZE + 2 + n] = (float)kS;
        }
    }
    #pragma unroll
    for (int ch = 0; ch < 8; ch++)
        #pragma unroll
        for (int j = 0; j < 4; j++) atomicAdd(&sAcc[ch*128 + lane*4 + j], pAcc[ch][j]);
    __syncthreads();
    for (int i = tid; i < MM; i += 256) atomicAdd(&g_avgp[i], sAcc[i]);
}

__global__ void k_finalize(float* __restrict__ out) {
    __shared__ float s1[MM];
    __shared__ float s2[MM];
    int m = threadIdx.x;
    float hp = (float)g_hist[m] * (1.f/(float)NN);
    float ap = g_avgp[m] * (1.f/(float)NN);
    s1[m] = -hp * log2f(hp + 1e-10f);
    s2[m] = -ap * log2f(ap + 1e-10f);
    __syncthreads();
    for (int s = 512; s > 0; s >>= 1) {
        if (m < s) { s1[m] += s1[m + s]; s2[m] += s2[m + s]; }
        __syncthreads();
    }
    if (m == 0) { out[QSIZE] = s1[0]; out[QSIZE + 1] = s2[0]; }
}

// ---------------- fuse2 ------------------------------------------------------
__global__ void __launch_bounds__(256) k_f2(const float* __restrict__ a2p,
                                            float* __restrict__ out) {
    __shared__ float sA[16][68];
    __shared__ float sB[16][68];
    int b = blockIdx.z, t0 = blockIdx.x*64, o0 = blockIdx.y*64;
    int tid = threadIdx.x;
    int tx = tid & 15, ty = tid >> 4;
    int kl = tid >> 4, nl4 = (tid & 15)*4;
    float acc[4][4] = {};
    const float* Ab = g_ctxout + (size_t)b*DD*TT;
    for (int kc = 0; kc < DD; kc += 16) {
        *(float4*)&sA[kl][nl4] = *(const float4*)(Ab + (size_t)(kc + kl)*TT + t0 + nl4);
        *(float4*)&sB[kl][nl4] = *(const float4*)(g_w2T + (size_t)(DD + kc + kl)*DD + o0 + nl4);
        __syncthreads();
        #pragma unroll
        for (int k = 0; k < 16; k++) {
            float4 av = *(const float4*)&sA[k][4*tx];
            float4 bv = *(const float4*)&sB[k][4*ty];
            float ar[4] = {av.x, av.y, av.z, av.w};
            float br[4] = {bv.x, bv.y, bv.z, bv.w};
            #pragma unroll
            for (int a = 0; a < 4; a++)
                #pragma unroll
                for (int c = 0; c < 4; c++)
                    acc[a][c] += br[a] * ar[c];
        }
        __syncthreads();
    }
    float a2 = *a2p;
    #pragma unroll
    for (int c = 0; c < 4; c++) {
        size_t n = (size_t)b*TT + t0 + 4*tx + c;
        int mi = g_idx[n];
        float4 wv = *(const float4*)&g_W2E[(size_t)mi*DD + o0 + 4*ty];
        float wr[4] = {wv.x, wv.y, wv.z, wv.w};
        float4 v;
        float u;
        u = acc[0][c] + wr[0]; v.x = (u >= 0.f) ? u : a2*u;
        u = acc[1][c] + wr[1]; v.y = (u >= 0.f) ? u : a2*u;
        u = acc[2][c] + wr[2]; v.z = (u >= 0.f) ? u : a2*u;
        u = acc[3][c] + wr[3]; v.w = (u >= 0.f) ? u : a2*u;
        *(float4*)&out[n*DD + o0 + 4*ty] = v;
    }
}

// ---------------- launch -----------------------------------------------------
extern "C" void kernel_launch(void* const* d_in, const int* in_sizes, int n_in,
                              void* d_out, int out_size) {
    const float* x     = (const float*)d_in[0];
    const float* noise = (const float*)d_in[1];
    const float* gum   = (const float*)d_in[2];
    const int*   epo   = (const int*)  d_in[3];
    const float* emb   = (const float*)d_in[4];
    const float* wctx  = (const float*)d_in[5];
    const float* wf1   = (const float*)d_in[6];
    const float* a1    = (const float*)d_in[7];
    const float* wf2   = (const float*)d_in[8];
    const float* a2    = (const float*)d_in[9];
    float* out = (float*)d_out;

    cudaFuncSetAttribute(k_dist_mma, cudaFuncAttributeMaxDynamicSharedMemorySize, D_SMEMB);

    dim3 tb32(32, 8);

    k_zero<<<4, 256>>>();
    k_transp<<<dim3(DD/32, MM/32), tb32>>>(emb, MM, DD, 0);      // E -> ET
    k_transp<<<dim3(2*DD/32, DD/32), tb32>>>(wf1, DD, 2*DD, 1);  // w_f1 -> w1T
    k_transp<<<dim3(2*DD/32, DD/32), tb32>>>(wf2, DD, 2*DD, 2);  // w_f2 -> w2T
    k_esq<<<MM/8, 256>>>(emb);
    k_split_e<<<MM*DD/256, 256>>>(emb);
    k_scale<<<BB, 256>>>(x, epo);
    k_xt<<<dim3(TT/32, DD/32, BB), tb32>>>(x);
    k_noisy<<<dim3((LL + 31)/32, DD/32, BB), tb32>>>(x, noise);
    k_conv<<<dim3(TT/64, DD/64, BB), 256>>>(wctx);
    k_f1<<<dim3(TT/64, DD/64, BB), 256>>>(a1);
    k_gemm_w2e<<<dim3(MM/64, DD/64), 256>>>();
    k_dist_mma<<<dim3(NN/128, MM/128), 256, D_SMEMB>>>();
    k_rowstats<<<NN/128, 256>>>(gum, emb, out);
    k_finalize<<<1, MM>>>(out);
    k_f2<<<dim3(TT/64, DD/64, BB), 256>>>(a2, out);
}

// round 5
// speedup vs baseline: 1.1663x; 1.1332x over previous
#include <cuda_runtime.h>
#include <math.h>
#include <stdint.h>

#define BB 8
#define TT 4096
#define DD 256
#define MM 1024
#define CTX 7
#define LL (TT - 1 + CTX)      /* 4102 */
#define LLP 4104               /* padded stride, 16B-aligned rows */
#define NN (BB*TT)             /* 32768 */
#define QSIZE (NN*DD)          /* 8388608 */

// ---------------- scratch (static device globals; no runtime alloc) ----------
__device__ __align__(16) float g_xt[BB*DD*TT];          // x transposed [b][d][t]
__device__ __align__(16) float g_noisy_hi[BB*DD*LLP];   // noisy ctx input, tf32-hi
__device__ __align__(16) float g_noisy_lo[BB*DD*LLP];   // residual (tf32)
__device__ __align__(16) float g_wch[DD*DD*CTX];        // w_ctx hi, A-frag shuffled
__device__ __align__(16) float g_wcl[DD*DD*CTX];        // w_ctx lo, A-frag shuffled
__device__ __align__(16) float g_ctxout[BB*DD*TT];      // conv output [b][o][t]
__device__ __align__(16) float g_cur[(size_t)NN*DD];    // fuse1 out [n][c], exact fp32
__device__ __align__(16) float g_cur_hi[(size_t)NN*DD]; // tf32-hi
__device__ __align__(16) float g_cur_lo[(size_t)NN*DD]; // residual (tf32)
__device__ __align__(16) float g_E_hi[MM*DD];
__device__ __align__(16) float g_E_lo[MM*DD];
__device__ __align__(16) float g_G[(size_t)NN*MM];      // cur . E^T   [n][m]
__device__ __align__(16) float g_ET[DD*MM];             // E transposed [c][m]
__device__ __align__(16) float g_w1T[2*DD*DD];          // w_f1 transposed [k][o]
__device__ __align__(16) float g_w2T[2*DD*DD];          // w_f2 transposed [k][o]
__device__ __align__(16) float g_W2E[MM*DD];            // E . w_f2a^T  [m][o]
__device__ __align__(16) float g_esq[MM];
__device__ float g_scale[BB];
__device__ int   g_idx[NN];
__device__ unsigned int g_hist[MM];
__device__ float g_avgp[MM];

__device__ __forceinline__ float tf32_hi(float v) {
    uint32_t b;
    asm("cvt.rna.tf32.f32 %0, %1;" : "=r"(b) : "f"(v));
    return __uint_as_float(b);
}

#define MMA8(d, a0,a1,a2,a3, b0,b1) \
    asm volatile("mma.sync.aligned.m16n8k8.row.col.f32.tf32.tf32.f32 " \
        "{%0,%1,%2,%3}, {%4,%5,%6,%7}, {%8,%9}, {%0,%1,%2,%3};" \
        : "+f"((d)[0]), "+f"((d)[1]), "+f"((d)[2]), "+f"((d)[3]) \
        : "r"(a0), "r"(a1), "r"(a2), "r"(a3), "r"(b0), "r"(b1))

// ---------------- small utility kernels -------------------------------------
__global__ void k_zero() {
    int i = blockIdx.x*blockDim.x + threadIdx.x;
    if (i < MM) { g_hist[i] = 0u; g_avgp[i] = 0.f; }
}

// dst[c][r] = src[r][c];  which: 0 -> g_ET, 1 -> g_w1T, 2 -> g_w2T
__global__ void k_transp(const float* __restrict__ src, int rows, int cols, int which) {
    __shared__ float s[32][33];
    float* dst = (which == 0) ? g_ET : (which == 1) ? g_w1T : g_w2T;
    int c0 = blockIdx.x*32, r0 = blockIdx.y*32;
    int tx = threadIdx.x, ty = threadIdx.y;
    #pragma unroll
    for (int j = 0; j < 4; j++) {
        int r = r0 + ty + j*8, c = c0 + tx;
        s[ty + j*8][tx] = (r < rows && c < cols) ? src[(size_t)r*cols + c] : 0.f;
    }
    __syncthreads();
    #pragma unroll
    for (int j = 0; j < 4; j++) {
        int c = c0 + ty + j*8, r = r0 + tx;
        if (c < cols && r < rows) dst[(size_t)c*rows + r] = s[tx][ty + j*8];
    }
}

__global__ void k_esq(const float* __restrict__ E) {
    int warp = threadIdx.x >> 5, lane = threadIdx.x & 31;
    int m = blockIdx.x*8 + warp;
    const float* row = E + (size_t)m*DD;
    float s = 0.f;
    for (int c = lane; c < DD; c += 32) { float v = row[c]; s += v*v; }
    #pragma unroll
    for (int o = 16; o > 0; o >>= 1) s += __shfl_down_sync(0xffffffffu, s, o);
    if (lane == 0) g_esq[m] = s;
}

__global__ void k_split_e(const float* __restrict__ E) {
    int i = blockIdx.x*256 + threadIdx.x;
    float v = E[i];
    float h = tf32_hi(v);
    g_E_hi[i] = h;
    g_E_lo[i] = tf32_hi(v - h);
}

// split w_ctx into tf32 hi/lo, stored in A-fragment-shuffled layout:
// dest[((ic*7+kk)*16 + otile)*128 + lane*4 + reg]
// lane = (o_loc&7)*4 + (i_loc&3);  reg = (o_loc>>3) + 2*(i_loc>>2)
__global__ void k_splitw(const float* __restrict__ wctx) {
    int idx = blockIdx.x*256 + threadIdx.x;       // grid 1792
    int o = idx / (DD*CTX);
    int rem = idx - o*(DD*CTX);
    int i = rem / CTX, kk = rem - i*CTX;
    float v = wctx[idx];
    float h = tf32_hi(v);
    int ic = i >> 3, il = i & 7;
    int otile = o >> 4, oloc = o & 15;
    int lane = (oloc & 7)*4 + (il & 3);
    int reg = (oloc >> 3) + 2*(il >> 2);
    int d = ((ic*7 + kk)*16 + otile)*128 + lane*4 + reg;
    g_wch[d] = h;
    g_wcl[d] = tf32_hi(v - h);
}

// scale[b] = 0.5 * sqrt(mean(ctx_in^2)) * 0.5^(epo/10)
__global__ void k_scale(const float* __restrict__ x, const int* __restrict__ epo_p) {
    int b = blockIdx.x;
    const float* xb = x + (size_t)b*TT*DD;
    float s = 0.f;
    int tot = (TT-1)*DD;
    for (int i = threadIdx.x; i < tot; i += blockDim.x) { float v = xb[i]; s += v*v; }
    __shared__ float sm[8];
    #pragma unroll
    for (int o = 16; o > 0; o >>= 1) s += __shfl_down_sync(0xffffffffu, s, o);
    if ((threadIdx.x & 31) == 0) sm[threadIdx.x >> 5] = s;
    __syncthreads();
    if (threadIdx.x == 0) {
        float t = 0.f;
        for (int w = 0; w < 8; w++) t += sm[w];
        int iv = epo_p[0];
        float ef = (iv >= 0 && iv < 100000) ? (float)iv : __int_as_float(iv);
        float sc = sqrtf(t / (float)(DD*LL));
        g_scale[b] = 0.5f * sc * exp2f(-ef * 0.1f);
    }
}

// g_xt[b][d][t] = x[b][t][d]
__global__ void k_xt(const float* __restrict__ x) {
    __shared__ float s[32][33];
    int b = blockIdx.z, t0 = blockIdx.x*32, d0 = blockIdx.y*32;
    int tx = threadIdx.x, ty = threadIdx.y;
    #pragma unroll
    for (int j = 0; j < 4; j++) {
        int t = t0 + ty + j*8;
        s[ty + j*8][tx] = x[((size_t)b*TT + t)*DD + d0 + tx];
    }
    __syncthreads();
    #pragma unroll
    for (int j = 0; j < 4; j++) {
        int d = d0 + ty + j*8;
        g_xt[((size_t)b*DD + d)*TT + t0 + tx] = s[tx][ty + j*8];
    }
}

// noisy[b][i][l] = pad(x) + coef*noise, split into tf32 hi/lo (stride LLP)
__global__ void k_noisy(const float* __restrict__ x, const float* __restrict__ noise) {
    __shared__ float s[32][33];
    int b = blockIdx.z, l0 = blockIdx.x*32, i0 = blockIdx.y*32;
    int tx = threadIdx.x, ty = threadIdx.y;
    float coef = g_scale[b];
    #pragma unroll
    for (int j = 0; j < 4; j++) {
        int row = ty + j*8;
        int t = l0 + row - CTX;
        float v = (t >= 0 && t < TT-1) ? x[((size_t)b*TT + t)*DD + i0 + tx] : 0.f;
        s[row][tx] = v;
    }
    __syncthreads();
    #pragma unroll
    for (int j = 0; j < 4; j++) {
        int i = i0 + ty + j*8, l = l0 + tx;
        if (l < LL) {
            float v = s[tx][ty + j*8] + coef * noise[((size_t)b*DD + i)*LL + l];
            float h = tf32_hi(v);
            size_t off = ((size_t)b*DD + i)*LLP + l;
            g_noisy_hi[off] = h;
            g_noisy_lo[off] = tf32_hi(v - h);
        }
    }
}

// ---------------- conv on tensor cores (3xTF32 implicit GEMM) ----------------
// ctx_out[b][o][t] = sum_{i,kk} w[o][i][kk] * noisy[b][i][t+kk]
// block: o64 x t128, warps 2(o) x 4(t), warp tile o32 x t32 (mf2 x nf4)
// k-loop: 32 i-chunks of 8, x 7 kk
#define CV_STG 9344  /* floats per stage: X hi/lo 2*1088 + W hi/lo 2*3584 */
#define CV_SMEMB (2*CV_STG*4)

__global__ void __launch_bounds__(256) k_conv_tc(int obase) {
    extern __shared__ float cs[];
    int tid = threadIdx.x, lane = tid & 31, warp = tid >> 5;
    int warpM = warp >> 2, warpN = warp & 3;
    int t0 = blockIdx.x*128, o0 = obase + blockIdx.y*64, b = blockIdx.z;
    int ot0 = o0 >> 4;

    uint32_t sbase;
    asm("{ .reg .u64 t; cvta.to.shared.u64 t, %1; cvt.u32.u64 %0, t; }" : "=r"(sbase) : "l"(cs));

    auto issue = [&](int ic, int s) {
        const float* xh = g_noisy_hi + ((size_t)(b*DD + ic*8))*LLP + t0;
        const float* xl = g_noisy_lo + ((size_t)(b*DD + ic*8))*LLP + t0;
        uint32_t xdh = sbase + (uint32_t)((s*CV_STG)*4);
        uint32_t xdl = xdh + 1088*4;
        for (int idx = tid; idx < 272; idx += 256) {
            int row = idx / 34, q = idx - row*34;
            asm volatile("cp.async.cg.shared.global [%0], [%1], 16;"
                :: "r"(xdh + (uint32_t)((row*136 + q*4)*4)), "l"(xh + (size_t)row*LLP + q*4));
            asm volatile("cp.async.cg.shared.global [%0], [%1], 16;"
                :: "r"(xdl + (uint32_t)((row*136 + q*4)*4)), "l"(xl + (size_t)row*LLP + q*4));
        }
        const float* wh = g_wch + ((size_t)(ic*7)*16 + ot0)*128;
        const float* wl = g_wcl + ((size_t)(ic*7)*16 + ot0)*128;
        uint32_t wdh = sbase + (uint32_t)((s*CV_STG + 2176)*4);
        uint32_t wdl = wdh + 3584*4;
        for (int idx = tid; idx < 896; idx += 256) {
            int kk = idx >> 7, q = idx & 127;
            asm volatile("cp.async.cg.shared.global [%0], [%1], 16;"
                :: "r"(wdh + (uint32_t)((kk*512 + q*4)*4)), "l"(wh + kk*2048 + q*4));
            asm volatile("cp.async.cg.shared.global [%0], [%1], 16;"
                :: "r"(wdl + (uint32_t)((kk*512 + q*4)*4)), "l"(wl + kk*2048 + q*4));
        }
        asm volatile("cp.async.commit_group;");
    };

    float c[2][4][4] = {};
    issue(0, 0);
    issue(1, 1);

    for (int ic = 0; ic < 32; ic++) {
        int s = ic & 1;
        if (ic < 31) { asm volatile("cp.async.wait_group 1;"); }
        else         { asm volatile("cp.async.wait_group 0;"); }
        __syncthreads();
        const float* XH = cs + s*CV_STG;
        const float* XL = XH + 1088;
        const float* WH = XH + 2176;
        const float* WL = XH + 5760;
        int i0v = lane & 3, trow = lane >> 2;

        #pragma unroll
        for (int kk = 0; kk < 7; kk++) {
            uint32_t ah[2][4], al[2][4];
            #pragma unroll
            for (int mf = 0; mf < 2; mf++) {
                float4 vh = *(const float4*)&WH[kk*512 + (warpM*2 + mf)*128 + lane*4];
                float4 vl = *(const float4*)&WL[kk*512 + (warpM*2 + mf)*128 + lane*4];
                ah[mf][0] = __float_as_uint(vh.x); ah[mf][1] = __float_as_uint(vh.y);
                ah[mf][2] = __float_as_uint(vh.z); ah[mf][3] = __float_as_uint(vh.w);
                al[mf][0] = __float_as_uint(vl.x); al[mf][1] = __float_as_uint(vl.y);
                al[mf][2] = __float_as_uint(vl.z); al[mf][3] = __float_as_uint(vl.w);
            }
            uint32_t bh[4][2], bl[4][2];
            #pragma unroll
            for (int nf = 0; nf < 4; nf++) {
                int toff = warpN*32 + nf*8 + trow + kk;
                bh[nf][0] = __float_as_uint(XH[i0v*136 + toff]);
                bh[nf][1] = __float_as_uint(XH[(i0v + 4)*136 + toff]);
                bl[nf][0] = __float_as_uint(XL[i0v*136 + toff]);
                bl[nf][1] = __float_as_uint(XL[(i0v + 4)*136 + toff]);
            }
            #pragma unroll
            for (int mf = 0; mf < 2; mf++) {
                #pragma unroll
                for (int nf = 0; nf < 4; nf++) {
                    MMA8(c[mf][nf], ah[mf][0], ah[mf][1], ah[mf][2], ah[mf][3], bh[nf][0], bh[nf][1]);
                    MMA8(c[mf][nf], ah[mf][0], ah[mf][1], ah[mf][2], ah[mf][3], bl[nf][0], bl[nf][1]);
                    MMA8(c[mf][nf], al[mf][0], al[mf][1], al[mf][2], al[mf][3], bh[nf][0], bh[nf][1]);
                }
            }
        }
        __syncthreads();
        if (ic + 2 < 32) issue(ic + 2, s);
    }

    #pragma unroll
    for (int mf = 0; mf < 2; mf++) {
        int r = o0 + warpM*32 + mf*16 + (lane >> 2);
        #pragma unroll
        for (int nf = 0; nf < 4; nf++) {
            int tg = t0 + warpN*32 + nf*8 + (lane & 3)*2;
            *(float2*)&g_ctxout[((size_t)b*DD + r)*TT + tg]     = make_float2(c[mf][nf][0], c[mf][nf][1]);
            *(float2*)&g_ctxout[((size_t)b*DD + r + 8)*TT + tg] = make_float2(c[mf][nf][2], c[mf][nf][3]);
        }
    }
}

// ---------------- fuse1: cur[n][o] = prelu(sum_k w1T[k][o]*Acat[k][t], a1)
__global__ void __launch_bounds__(256) k_f1(const float* __restrict__ a1p) {
    __shared__ float sA[16][68];
    __shared__ float sB[16][68];
    int b = blockIdx.z, t0 = blockIdx.x*64, o0 = blockIdx.y*64;
    int tid = threadIdx.x;
    int tx = tid & 15, ty = tid >> 4;
    int kl = tid >> 4, nl4 = (tid & 15)*4;
    float acc[4][4] = {};
    for (int kc = 0; kc < 2*DD; kc += 16) {
        const float* Ap = (kc < DD) ? (g_xt + ((size_t)b*DD + kc)*TT)
                                    : (g_ctxout + ((size_t)b*DD + (kc - DD))*TT);
        *(float4*)&sA[kl][nl4] = *(const float4*)(Ap + (size_t)kl*TT + t0 + nl4);
        *(float4*)&sB[kl][nl4] = *(const float4*)(g_w1T + (size_t)(kc + kl)*DD + o0 + nl4);
        __syncthreads();
        #pragma unroll
        for (int k = 0; k < 16; k++) {
            float4 av = *(const float4*)&sA[k][4*tx];
            float4 bv = *(const float4*)&sB[k][4*ty];
            float ar[4] = {av.x, av.y, av.z, av.w};
            float br[4] = {bv.x, bv.y, bv.z, bv.w};
            #pragma unroll
            for (int a = 0; a < 4; a++)
                #pragma unroll
                for (int c = 0; c < 4; c++)
                    acc[a][c] += br[a] * ar[c];
        }
        __syncthreads();
    }
    float a1 = *a1p;
    #pragma unroll
    for (int c = 0; c < 4; c++) {
        size_t n = (size_t)b*TT + t0 + 4*tx + c;
        float4 ve, vh, vl;
        float u, h;
        u = acc[0][c]; u = (u >= 0.f) ? u : a1*u; ve.x = u; h = tf32_hi(u); vh.x = h; vl.x = tf32_hi(u - h);
        u = acc[1][c]; u = (u >= 0.f) ? u : a1*u; ve.y = u; h = tf32_hi(u); vh.y = h; vl.y = tf32_hi(u - h);
        u = acc[2][c]; u = (u >= 0.f) ? u : a1*u; ve.z = u; h = tf32_hi(u); vh.z = h; vl.z = tf32_hi(u - h);
        u = acc[3][c]; u = (u >= 0.f) ? u : a1*u; ve.w = u; h = tf32_hi(u); vh.w = h; vl.w = tf32_hi(u - h);
        *(float4*)&g_cur[n*DD + o0 + 4*ty] = ve;
        *(float4*)&g_cur_hi[n*DD + o0 + 4*ty] = vh;
        *(float4*)&g_cur_lo[n*DD + o0 + 4*ty] = vl;
    }
}

// ---------------- W2E GEMM (small): C[m][o] = sum_c ET[c][m] w2T[c][o]
__global__ void __launch_bounds__(256) k_gemm_w2e() {
    __shared__ float sA[16][68];
    __shared__ float sB[16][68];
    int i0 = blockIdx.x*64, j0 = blockIdx.y*64;
    int tid = threadIdx.x;
    int tx = tid & 15, ty = tid >> 4;
    int kl = tid >> 4, nl4 = (tid & 15)*4;
    float acc[4][4] = {};
    for (int kc = 0; kc < DD; kc += 16) {
        *(float4*)&sA[kl][nl4] = *(const float4*)(g_ET  + (size_t)(kc + kl)*MM + i0 + nl4);
        *(float4*)&sB[kl][nl4] = *(const float4*)(g_w2T + (size_t)(kc + kl)*DD + j0 + nl4);
        __syncthreads();
        #pragma unroll
        for (int k = 0; k < 16; k++) {
            float4 av = *(const float4*)&sA[k][4*tx];
            float4 bv = *(const float4*)&sB[k][4*ty];
            float ar[4] = {av.x, av.y, av.z, av.w};
            float br[4] = {bv.x, bv.y, bv.z, bv.w};
            #pragma unroll
            for (int a = 0; a < 4; a++)
                #pragma unroll
                for (int c = 0; c < 4; c++)
                    acc[a][c] += br[a] * ar[c];
        }
        __syncthreads();
    }
    #pragma unroll
    for (int c = 0; c < 4; c++) {
        int i = i0 + 4*tx + c;
        float4 v = make_float4(acc[0][c], acc[1][c], acc[2][c], acc[3][c]);
        *(float4*)&g_W2E[(size_t)i*DD + j0 + 4*ty] = v;
    }
}

// ---------------- dist GEMM via mma.sync tf32 (3xTF32) -----------------------
#define D_ARRF 4096
#define D_SMEMB (2*4*D_ARRF*4)

__device__ __forceinline__ int swz(int r, int c) {
    return r*32 + ((((c >> 2) ^ (r & 7)) << 2) | (c & 3));
}

__global__ void __launch_bounds__(256) k_dist_mma() {
    extern __shared__ float sm[];
    int tid = threadIdx.x, lane = tid & 31, warp = tid >> 5;
    int warpM = warp >> 2, warpN = warp & 3;
    int n0 = blockIdx.x*128, m0 = blockIdx.y*128;

    uint32_t sbase;
    asm("{ .reg .u64 t; cvta.to.shared.u64 t, %1; cvt.u32.u64 %0, t; }" : "=r"(sbase) : "l"(sm));

    const float* srcs[4] = { g_cur_hi + (size_t)n0*DD, g_cur_lo + (size_t)n0*DD,
                             g_E_hi   + (size_t)m0*DD, g_E_lo   + (size_t)m0*DD };
    int lr = tid >> 3, c4 = tid & 7;

    auto issue = [&](int kc, int s) {
        #pragma unroll
        for (int a = 0; a < 4; a++) {
            const float* srcb = srcs[a] + kc + c4*4;
            uint32_t dstb = sbase + (uint32_t)(((s*4 + a)*D_ARRF)*4);
            #pragma unroll
            for (int j = 0; j < 4; j++) {
                int row = lr + 32*j;
                uint32_t dst = dstb + (uint32_t)((row*32 + ((c4 ^ (row & 7)) << 2))*4);
                const float* src = srcb + (size_t)row*DD;
                asm volatile("cp.async.cg.shared.global [%0], [%1], 16;"
                             :: "r"(dst), "l"(src));
            }
        }
        asm volatile("cp.async.commit_group;");
    };

    float c[4][4][4] = {};
    issue(0, 0);

    for (int it = 0; it < 8; it++) {
        int s = it & 1;
        if (it + 1 < 8) issue((it + 1)*32, s ^ 1);
        if (it + 1 < 8) { asm volatile("cp.async.wait_group 1;"); }
        else            { asm volatile("cp.async.wait_group 0;"); }
        __syncthreads();

        const float* sAh = sm + (s*4 + 0)*D_ARRF;
        const float* sAl = sm + (s*4 + 1)*D_ARRF;
        const float* sBh = sm + (s*4 + 2)*D_ARRF;
        const float* sBl = sm + (s*4 + 3)*D_ARRF;

        #pragma unroll
        for (int ks = 0; ks < 4; ks++) {
            int ca = ks*8 + (lane & 3);
            uint32_t Ah[16], Al[16], Bh[8], Bl[8];
            #pragma unroll
            for (int mf = 0; mf < 4; mf++) {
                int r1 = warpM*64 + mf*16 + (lane >> 2), r2 = r1 + 8;
                Ah[mf*4+0] = __float_as_uint(sAh[swz(r1, ca)]);
                Ah[mf*4+1] = __float_as_uint(sAh[swz(r2, ca)]);
                Ah[mf*4+2] = __float_as_uint(sAh[swz(r1, ca + 4)]);
                Ah[mf*4+3] = __float_as_uint(sAh[swz(r2, ca + 4)]);
                Al[mf*4+0] = __float_as_uint(sAl[swz(r1, ca)]);
                Al[mf*4+1] = __float_as_uint(sAl[swz(r2, ca)]);
                Al[mf*4+2] = __float_as_uint(sAl[swz(r1, ca + 4)]);
                Al[mf*4+3] = __float_as_uint(sAl[swz(r2, ca + 4)]);
            }
            #pragma unroll
            for (int nf = 0; nf < 4; nf++) {
                int rm = warpN*32 + nf*8 + (lane >> 2);
                Bh[nf*2+0] = __float_as_uint(sBh[swz(rm, ca)]);
                Bh[nf*2+1] = __float_as_uint(sBh[swz(rm, ca + 4)]);
                Bl[nf*2+0] = __float_as_uint(sBl[swz(rm, ca)]);
                Bl[nf*2+1] = __float_as_uint(sBl[swz(rm, ca + 4)]);
            }
            #pragma unroll
            for (int mf = 0; mf < 4; mf++) {
                #pragma unroll
                for (int nf = 0; nf < 4; nf++) {
                    MMA8(c[mf][nf], Ah[mf*4+0], Ah[mf*4+1], Ah[mf*4+2], Ah[mf*4+3],
                         Bh[nf*2+0], Bh[nf*2+1]);
                    MMA8(c[mf][nf], Ah[mf*4+0], Ah[mf*4+1], Ah[mf*4+2], Ah[mf*4+3],
                         Bl[nf*2+0], Bl[nf*2+1]);
                    MMA8(c[mf][nf], Al[mf*4+0], Al[mf*4+1], Al[mf*4+2], Al[mf*4+3],
                         Bh[nf*2+0], Bh[nf*2+1]);
                }
            }
        }
        __syncthreads();
    }

    #pragma unroll
    for (int mf = 0; mf < 4; mf++) {
        int r1 = n0 + warpM*64 + mf*16 + (lane >> 2);
        #pragma unroll
        for (int nf = 0; nf < 4; nf++) {
            int gc = m0 + warpN*32 + nf*8 + (lane & 3)*2;
            *(float2*)&g_G[(size_t)r1*MM + gc]       = make_float2(c[mf][nf][0], c[mf][nf][1]);
            *(float2*)&g_G[(size_t)(r1 + 8)*MM + gc] = make_float2(c[mf][nf][2], c[mf][nf][3]);
        }
    }
}

// ---------------- per-row stats with exact top-2 refinement -----------------
__device__ __forceinline__ float gumbel_of(float u) {
    u = fminf(fmaxf(u, 1e-10f), 1.f - 1e-7f);
    return -logf(-logf(u));
}

__global__ void __launch_bounds__(256) k_rowstats(const float* __restrict__ gum,
                                                  const float* __restrict__ emb,
                                                  float* __restrict__ out) {
    __shared__ float sAcc[MM];
    int tid = threadIdx.x, wid = tid >> 5, lane = tid & 31;
    for (int i = tid; i < MM; i += 256) sAcc[i] = 0.f;
    __syncthreads();

    float esq_r[8][4];
    #pragma unroll
    for (int ch = 0; ch < 8; ch++) {
        float4 v = *(const float4*)&g_esq[ch*128 + lane*4];
        esq_r[ch][0] = v.x; esq_r[ch][1] = v.y; esq_r[ch][2] = v.z; esq_r[ch][3] = v.w;
    }
    float pAcc[8][4] = {};
    int nbase = blockIdx.x*128 + wid*16;

    for (int r = 0; r < 16; r++) {
        int n = nbase + r;
        const float* Gr = g_G + (size_t)n*MM;
        const float* Ur = gum + (size_t)n*MM;
        float dm[8][4];
        float h1v = -3.4e38f, h2v = -3.4e38f; int h1i = 0x7fffffff, h2i = 0x7fffffff;
        float s1v = -3.4e38f, s2v = -3.4e38f; int s1i = 0x7fffffff, s2i = 0x7fffffff;
        #pragma unroll
        for (int ch = 0; ch < 8; ch++) {
            float4 g4 = *(const float4*)&Gr[ch*128 + lane*4];
            float4 u4 = *(const float4*)&Ur[ch*128 + lane*4];
            float gg[4] = {g4.x, g4.y, g4.z, g4.w};
            float uu[4] = {u4.x, u4.y, u4.z, u4.w};
            #pragma unroll
            for (int j = 0; j < 4; j++) {
                int m = ch*128 + lane*4 + j;
                float d = 2.f*gg[j] - esq_r[ch][j];
                dm[ch][j] = d;
                if (d > h1v || (d == h1v && m < h1i)) { h2v = h1v; h2i = h1i; h1v = d; h1i = m; }
                else if (d > h2v || (d == h2v && m < h2i)) { h2v = d; h2i = m; }
                float sc = d + gumbel_of(uu[j]);
                if (sc > s1v || (sc == s1v && m < s1i)) { s2v = s1v; s2i = s1i; s1v = sc; s1i = m; }
                else if (sc > s2v || (sc == s2v && m < s2i)) { s2v = sc; s2i = m; }
            }
        }
        #pragma unroll
        for (int o = 16; o > 0; o >>= 1) {
            float ov1 = __shfl_xor_sync(0xffffffffu, h1v, o);
            int   oi1 = __shfl_xor_sync(0xffffffffu, h1i, o);
            float ov2 = __shfl_xor_sync(0xffffffffu, h2v, o);
            int   oi2 = __shfl_xor_sync(0xffffffffu, h2i, o);
            if (ov1 > h1v || (ov1 == h1v && oi1 < h1i)) {
                float t1v = h1v; int t1i = h1i;
                h1v = ov1; h1i = oi1;
                if (t1v > ov2 || (t1v == ov2 && t1i < oi2)) { h2v = t1v; h2i = t1i; }
                else { h2v = ov2; h2i = oi2; }
            } else {
                if (ov1 > h2v || (ov1 == h2v && oi1 < h2i)) { h2v = ov1; h2i = oi1; }
            }
            float pv1 = __shfl_xor_sync(0xffffffffu, s1v, o);
            int   pi1 = __shfl_xor_sync(0xffffffffu, s1i, o);
            float pv2 = __shfl_xor_sync(0xffffffffu, s2v, o);
            int   pi2 = __shfl_xor_sync(0xffffffffu, s2i, o);
            if (pv1 > s1v || (pv1 == s1v && pi1 < s1i)) {
                float t1v = s1v; int t1i = s1i;
                s1v = pv1; s1i = pi1;
                if (t1v > pv2 || (t1v == pv2 && t1i < pi2)) { s2v = t1v; s2i = t1i; }
                else { s2v = pv2; s2i = pi2; }
            } else {
                if (pv1 > s2v || (pv1 == s2v && pi1 < s2i)) { s2v = pv1; s2i = pi1; }
            }
        }

        int cands[4] = {h1i, h2i, s1i, s2i};
        float ex[4];
        const float* curp = g_cur + (size_t)n*DD + lane*8;
        #pragma unroll
        for (int t = 0; t < 4; t++) {
            const float* Ep = emb + (size_t)cands[t]*DD + lane*8;
            float s = 0.f;
            #pragma unroll
            for (int j = 0; j < 8; j++) s += curp[j]*Ep[j];
            #pragma unroll
            for (int o = 16; o > 0; o >>= 1) s += __shfl_xor_sync(0xffffffffu, s, o);
            ex[t] = 2.f*s - g_esq[cands[t]];
        }

        float ssum = 0.f;
        #pragma unroll
        for (int ch = 0; ch < 8; ch++)
            #pragma unroll
            for (int j = 0; j < 4; j++) ssum += expf(dm[ch][j] - h1v);
        #pragma unroll
        for (int o = 16; o > 0; o >>= 1) ssum += __shfl_xor_sync(0xffffffffu, ssum, o);
        float inv = 1.f / ssum;
        #pragma unroll
        for (int ch = 0; ch < 8; ch++)
            #pragma unroll
            for (int j = 0; j < 4; j++) pAcc[ch][j] += expf(dm[ch][j] - h1v) * inv;

        if (lane == 0) {
            int kH = h1i; float vH = ex[0];
            if (ex[1] > vH || (ex[1] == vH && h2i < kH)) { kH = h2i; vH = ex[1]; }
            atomicAdd(&g_hist[kH], 1u);
            float sc0 = ex[2] + gumbel_of(Ur[s1i]);
            float sc1 = ex[3] + gumbel_of(Ur[s2i]);
            int kS = s1i;
            if (sc1 > sc0 || (sc1 == sc0 && s2i < s1i)) kS = s2i;
            g_idx[n] = kS;
            out[QSIZE + 2 + n] = (float)kS;
        }
    }
    #pragma unroll
    for (int ch = 0; ch < 8; ch++)
        #pragma unroll
        for (int j = 0; j < 4; j++) atomicAdd(&sAcc[ch*128 + lane*4 + j], pAcc[ch][j]);
    __syncthreads();
    for (int i = tid; i < MM; i += 256) atomicAdd(&g_avgp[i], sAcc[i]);
}

__global__ void k_finalize(float* __restrict__ out) {
    __shared__ float s1[MM];
    __shared__ float s2[MM];
    int m = threadIdx.x;
    float hp = (float)g_hist[m] * (1.f/(float)NN);
    float ap = g_avgp[m] * (1.f/(float)NN);
    s1[m] = -hp * log2f(hp + 1e-10f);
    s2[m] = -ap * log2f(ap + 1e-10f);
    __syncthreads();
    for (int s = 512; s > 0; s >>= 1) {
        if (m < s) { s1[m] += s1[m + s]; s2[m] += s2[m + s]; }
        __syncthreads();
    }
    if (m == 0) { out[QSIZE] = s1[0]; out[QSIZE + 1] = s2[0]; }
}

// ---------------- fuse2 ------------------------------------------------------
__global__ void __launch_bounds__(256) k_f2(const float* __restrict__ a2p,
                                            float* __restrict__ out) {
    __shared__ float sA[16][68];
    __shared__ float sB[16][68];
    int b = blockIdx.z, t0 = blockIdx.x*64, o0 = blockIdx.y*64;
    int tid = threadIdx.x;
    int tx = tid & 15, ty = tid >> 4;
    int kl = tid >> 4, nl4 = (tid & 15)*4;
    float acc[4][4] = {};
    const float* Ab = g_ctxout + (size_t)b*DD*TT;
    for (int kc = 0; kc < DD; kc += 16) {
        *(float4*)&sA[kl][nl4] = *(const float4*)(Ab + (size_t)(kc + kl)*TT + t0 + nl4);
        *(float4*)&sB[kl][nl4] = *(const float4*)(g_w2T + (size_t)(DD + kc + kl)*DD + o0 + nl4);
        __syncthreads();
        #pragma unroll
        for (int k = 0; k < 16; k++) {
            float4 av = *(const float4*)&sA[k][4*tx];
            float4 bv = *(const float4*)&sB[k][4*ty];
            float ar[4] = {av.x, av.y, av.z, av.w};
            float br[4] = {bv.x, bv.y, bv.z, bv.w};
            #pragma unroll
            for (int a = 0; a < 4; a++)
                #pragma unroll
                for (int c = 0; c < 4; c++)
                    acc[a][c] += br[a] * ar[c];
        }
        __syncthreads();
    }
    float a2 = *a2p;
    #pragma unroll
    for (int c = 0; c < 4; c++) {
        size_t n = (size_t)b*TT + t0 + 4*tx + c;
        int mi = g_idx[n];
        float4 wv = *(const float4*)&g_W2E[(size_t)mi*DD + o0 + 4*ty];
        float wr[4] = {wv.x, wv.y, wv.z, wv.w};
        float4 v;
        float u;
        u = acc[0][c] + wr[0]; v.x = (u >= 0.f) ? u : a2*u;
        u = acc[1][c] + wr[1]; v.y = (u >= 0.f) ? u : a2*u;
        u = acc[2][c] + wr[2]; v.z = (u >= 0.f) ? u : a2*u;
        u = acc[3][c] + wr[3]; v.w = (u >= 0.f) ? u : a2*u;
        *(float4*)&out[n*DD + o0 + 4*ty] = v;
    }
}

// ---------------- launch -----------------------------------------------------
extern "C" void kernel_launch(void* const* d_in, const int* in_sizes, int n_in,
                              void* d_out, int out_size) {
    const float* x     = (const float*)d_in[0];
    const float* noise = (const float*)d_in[1];
    const float* gum   = (const float*)d_in[2];
    const int*   epo   = (const int*)  d_in[3];
    const float* emb   = (const float*)d_in[4];
    const float* wctx  = (const float*)d_in[5];
    const float* wf1   = (const float*)d_in[6];
    const float* a1    = (const float*)d_in[7];
    const float* wf2   = (const float*)d_in[8];
    const float* a2    = (const float*)d_in[9];
    float* out = (float*)d_out;

    cudaFuncSetAttribute(k_conv_tc, cudaFuncAttributeMaxDynamicSharedMemorySize, CV_SMEMB);
    cudaFuncSetAttribute(k_dist_mma, cudaFuncAttributeMaxDynamicSharedMemorySize, D_SMEMB);

    dim3 tb32(32, 8);

    // order chosen so ncu -s 5 -c 1 lands on k_conv_tc (slot 5 or 6)
    k_scale<<<BB, 256>>>(x, epo);                                   // 0
    k_xt<<<dim3(TT/32, DD/32, BB), tb32>>>(x);                      // 1
    k_noisy<<<dim3((LL + 31)/32, DD/32, BB), tb32>>>(x, noise);     // 2
    k_splitw<<<DD*DD*CTX/256, 256>>>(wctx);                         // 3
    k_zero<<<4, 256>>>();                                           // 4
    k_conv_tc<<<dim3(TT/128, 2, BB), 256, CV_SMEMB>>>(0);           // 5
    k_conv_tc<<<dim3(TT/128, 2, BB), 256, CV_SMEMB>>>(128);         // 6
    k_transp<<<dim3(DD/32, MM/32), tb32>>>(emb, MM, DD, 0);         // ET
    k_transp<<<dim3(2*DD/32, DD/32), tb32>>>(wf1, DD, 2*DD, 1);     // w1T
    k_transp<<<dim3(2*DD/32, DD/32), tb32>>>(wf2, DD, 2*DD, 2);     // w2T
    k_esq<<<MM/8, 256>>>(emb);
    k_split_e<<<MM*DD/256, 256>>>(emb);
    k_f1<<<dim3(TT/64, DD/64, BB), 256>>>(a1);
    k_gemm_w2e<<<dim3(MM/64, DD/64), 256>>>();
    k_dist_mma<<<dim3(NN/128, MM/128), 256, D_SMEMB>>>();
    k_rowstats<<<NN/128, 256>>>(gum, emb, out);
    k_finalize<<<1, MM>>>(out);
    k_f2<<<dim3(TT/64, DD/64, BB), 256>>>(a2, out);
}